// round 1
// baseline (speedup 1.0000x reference)
#include <cuda_runtime.h>
#include <cstdint>
#include <cstddef>

#define T_   512
#define B_   128
#define I_   512
#define H_   512
#define G4_  2048
#define NCTA 256
#define NTHR 128

// ---------------- scratch (device globals; no allocation) ----------------
__device__ float    g_Wcat[1024 * 2048];   // [k][n]: k<512 -> w_ih, k>=512 -> w_hh (transposed)
__device__ float    g_h[2][B_ * H_];       // double-buffered pre-processed h
__device__ float    g_c[B_ * H_];          // pre-processed c (exclusive per-CTA tile ownership)
__device__ unsigned g_gen;
__device__ unsigned g_cnt;

// ---------------- grid-wide barrier (canonical fence+atomic pattern) -----
__device__ __forceinline__ void grid_bar() {
    __syncthreads();
    if (threadIdx.x == 0) {
        volatile unsigned* vg = &g_gen;
        unsigned my = *vg;
        __threadfence();
        unsigned prev = atomicAdd(&g_cnt, 1u);
        if (prev == NCTA - 1) {
            atomicExch(&g_cnt, 0u);
            __threadfence();
            atomicAdd(&g_gen, 1u);
        } else {
            while (*vg == my) { }
            __threadfence();
        }
    }
    __syncthreads();
}

__device__ __forceinline__ float sigf(float x) {
    return 1.0f / (1.0f + expf(-x));
}

// --------------------------------------------------------------------------
// Persistent LSTM kernel.
// Grid partition: blockIdx.x = bg*32 + cg
//   bg in [0,8): batch rows  [bg*16, bg*16+16)
//   cg in [0,32): h columns  [cg*16, cg*16+16)
// Each CTA computes the 16x64 gate tile (cols = q*16+jj, weight row n = q*512+j0+jj)
// over K=1024 (x part k<512, h part k>=512), then does gates + state update +
// next-step mask/noise locally. One grid barrier per step.
// --------------------------------------------------------------------------
__global__ void __launch_bounds__(NTHR, 2) lstm_persistent(
    const float*    __restrict__ latent,   // [T,B,I]
    const float*    __restrict__ h0,       // [1,B,H]
    const float*    __restrict__ c0,       // [1,B,H]
    const uint32_t* __restrict__ reset,    // [1,B,T,1] bool as 4-byte
    const uint32_t* __restrict__ clearm,   // [B,T]     bool as 4-byte
    const float*    __restrict__ nstd,     // [B,T]
    const float*    __restrict__ noise,    // [T,B,H]
    const float*    __restrict__ w_ih,     // [4H,I]
    const float*    __restrict__ w_hh,     // [4H,H]
    const float*    __restrict__ b_ih,     // [4H]
    const float*    __restrict__ b_hh,     // [4H]
    float*          __restrict__ out)      // hidden [T,B,H] ++ hN [B,H] ++ cN [B,H]
{
    __shared__ __align__(16) float A_s[2][32 * 18];   // [k][row] padded to 18
    __shared__ __align__(16) float B_s[2][32 * 64];   // [k][c]
    __shared__ float gsm[64 * 16];                    // [c][row]
    __shared__ float bias_s[64];

    const int tid = threadIdx.x;
    const int cb  = blockIdx.x;
    const int bg  = cb >> 5, cg = cb & 31;
    const int b0  = bg << 4, j0 = cg << 4;

    // compute-thread mapping: 2 rows x 4 cols per thread
    const int tr = tid & 7;    // row pair: rows tr*2, tr*2+1
    const int tc = tid >> 3;   // col quad: cols tc*4 .. tc*4+3

    // ---------------- init: build Wcat (transposed concat weights) ----------------
    {
        int gt = cb * NTHR + tid;
        for (int o = gt; o < 1024 * 2048; o += NCTA * NTHR) {
            int n = o & 2047, k = o >> 11;
            g_Wcat[o] = (k < 512) ? w_ih[n * 512 + k] : w_hh[n * 512 + (k - 512)];
        }
    }
    // bias for this CTA's 64 gate cols
    if (tid < 64) {
        int n = ((tid >> 4) << 9) + j0 + (tid & 15);
        bias_s[tid] = b_ih[n] + b_hh[n];
    }
    // init h/c for owned tile, with step-0 mask/noise pre-processing
    for (int e = tid; e < 256; e += NTHR) {
        int r = e & 15, jj = e >> 4;
        int b = b0 + r, j = j0 + jj;
        float h = h0[b * H_ + j];
        float c = c0[b * H_ + j];
        bool m = ((reset[b * T_ + 0] | clearm[b * T_ + 0]) != 0u);
        if (m) { h = 0.f; c = 0.f; }
        float nz = noise[(size_t)b * H_ + j] * nstd[b * T_ + 0];
        h += nz; c += nz;
        g_h[0][b * H_ + j] = h;
        g_c[b * H_ + j]    = c;
    }
    grid_bar();

    // tile-load thread mappings
    const int rowA = tid >> 3;            // 0..15
    const int kqA  = tid & 7;             // 0..7 -> k chunk of 4
    const int c0B  = (tid << 2) & 63;     // 0,4,...,60
    const int kkB  = tid >> 4;            // 0..7 (+8*m)
    const int nB   = ((c0B >> 4) << 9) + j0 + (c0B & 15);

    for (int t = 0; t < T_; ++t) {
        const float* __restrict__ xsrc = latent + (size_t)t * (B_ * I_);
        const float* __restrict__ hsrc = g_h[t & 1];

        float acc0[4], acc1[4];
        #pragma unroll
        for (int c = 0; c < 4; ++c) { acc0[c] = bias_s[tc * 4 + c]; acc1[c] = acc0[c]; }

        float  ra[4];
        float4 rb[4];

        auto LD = [&](int kt) {
            int k0 = kt << 5;
            const float* asrc = (k0 < 512)
                ? (xsrc + (b0 + rowA) * 512 + k0 + kqA * 4)
                : (hsrc + (b0 + rowA) * 512 + (k0 - 512) + kqA * 4);
            float4 av = *reinterpret_cast<const float4*>(asrc);
            ra[0] = av.x; ra[1] = av.y; ra[2] = av.z; ra[3] = av.w;
            #pragma unroll
            for (int m = 0; m < 4; ++m)
                rb[m] = *reinterpret_cast<const float4*>(
                    &g_Wcat[(size_t)(k0 + kkB + 8 * m) * 2048 + nB]);
        };
        auto ST = [&](int buf) {
            #pragma unroll
            for (int m = 0; m < 4; ++m)
                A_s[buf][(kqA * 4 + m) * 18 + rowA] = ra[m];
            #pragma unroll
            for (int m = 0; m < 4; ++m)
                *reinterpret_cast<float4*>(&B_s[buf][(kkB + 8 * m) * 64 + c0B]) = rb[m];
        };

        LD(0); ST(0);
        int buf = 0;
        for (int kt = 0; kt < 32; ++kt) {
            __syncthreads();
            if (kt < 31) LD(kt + 1);
            #pragma unroll
            for (int kk = 0; kk < 32; ++kk) {
                float2 a  = *reinterpret_cast<const float2*>(&A_s[buf][kk * 18 + tr * 2]);
                float4 bv = *reinterpret_cast<const float4*>(&B_s[buf][kk * 64 + tc * 4]);
                acc0[0] += a.x * bv.x; acc0[1] += a.x * bv.y;
                acc0[2] += a.x * bv.z; acc0[3] += a.x * bv.w;
                acc1[0] += a.y * bv.x; acc1[1] += a.y * bv.y;
                acc1[2] += a.y * bv.z; acc1[3] += a.y * bv.w;
            }
            if (kt < 31) ST(buf ^ 1);
            buf ^= 1;
        }

        // exchange gates through smem (each (b,j) needs i,f,g,o from 4 col groups)
        #pragma unroll
        for (int c = 0; c < 4; ++c) {
            gsm[(tc * 4 + c) * 16 + tr * 2]     = acc0[c];
            gsm[(tc * 4 + c) * 16 + tr * 2 + 1] = acc1[c];
        }
        __syncthreads();

        // gates + state update + next-step pre-elementwise (owned tile, 2 elems/thread)
        #pragma unroll
        for (int e2 = 0; e2 < 2; ++e2) {
            int e = tid + e2 * NTHR;
            int r = e & 15, jj = e >> 4;
            int b = b0 + r, j = j0 + jj;
            float gi = gsm[(jj)      * 16 + r];
            float gf = gsm[(16 + jj) * 16 + r];
            float gg = gsm[(32 + jj) * 16 + r];
            float go = gsm[(48 + jj) * 16 + r];
            float i_ = sigf(gi);
            float f_ = sigf(gf);
            float g_ = tanhf(gg);
            float o_ = sigf(go);
            float cp = g_c[b * H_ + j];
            float cn = f_ * cp + i_ * g_;
            float hn = o_ * tanhf(cn);

            out[(size_t)t * (B_ * H_) + b * H_ + j] = hn;

            float hw, cw;
            if (t + 1 < T_) {
                bool m = ((reset[b * T_ + (t + 1)] | clearm[b * T_ + (t + 1)]) != 0u);
                hw = m ? 0.f : hn;
                cw = m ? 0.f : cn;
                float nz = noise[(size_t)(t + 1) * (B_ * H_) + b * H_ + j]
                         * nstd[b * T_ + (t + 1)];
                hw += nz; cw += nz;
            } else {
                hw = hn; cw = cn;
                out[(size_t)T_ * (B_ * H_)            + b * H_ + j] = hn;   // hN
                out[(size_t)T_ * (B_ * H_) + B_ * H_  + b * H_ + j] = cn;   // cN
            }
            g_h[(t + 1) & 1][b * H_ + j] = hw;
            g_c[b * H_ + j]              = cw;
        }

        grid_bar();
    }
}

extern "C" void kernel_launch(void* const* d_in, const int* in_sizes, int n_in,
                              void* d_out, int out_size) {
    (void)in_sizes; (void)n_in; (void)out_size;
    const float*    latent = (const float*)d_in[0];
    const float*    h0     = (const float*)d_in[1];
    const float*    c0     = (const float*)d_in[2];
    const uint32_t* reset  = (const uint32_t*)d_in[3];
    const uint32_t* clearm = (const uint32_t*)d_in[4];
    const float*    nstd   = (const float*)d_in[5];
    const float*    noise  = (const float*)d_in[6];
    const float*    w_ih   = (const float*)d_in[7];
    const float*    w_hh   = (const float*)d_in[8];
    const float*    b_ih   = (const float*)d_in[9];
    const float*    b_hh   = (const float*)d_in[10];
    float* out = (float*)d_out;

    lstm_persistent<<<NCTA, NTHR>>>(latent, h0, c0, reset, clearm, nstd, noise,
                                    w_ih, w_hh, b_ih, b_hh, out);
}

// round 2
// speedup vs baseline: 1.7740x; 1.7740x over previous
#include <cuda_runtime.h>
#include <cstdint>
#include <cstddef>

#define T_   512
#define B_   128
#define H_   512
#define G4   2048
#define NCTA2 128

// ---------------- scratch (device globals; no allocation) ----------------
__device__ float    g_Xg[(size_t)T_ * B_ * G4];   // 512 MB: x@W_ih^T + b_ih + b_hh
__device__ float    g_h[2][B_ * H_];              // double-buffered pre-processed h (tf32-rounded)
__device__ unsigned g_gen;
__device__ unsigned g_cnt;

// ---------------- helpers ----------------
__device__ __forceinline__ uint32_t f2tf_u(float x) {
    uint32_t r; asm("cvt.rna.tf32.f32 %0, %1;" : "=r"(r) : "f"(x)); return r;
}
__device__ __forceinline__ float f2tf_f(float x) { return __uint_as_float(f2tf_u(x)); }

__device__ __forceinline__ void mma_tf32(float c[4],
        uint32_t a0, uint32_t a1, uint32_t a2, uint32_t a3,
        uint32_t b0, uint32_t b1) {
    asm volatile(
        "mma.sync.aligned.m16n8k8.row.col.f32.tf32.tf32.f32 "
        "{%0,%1,%2,%3},{%4,%5,%6,%7},{%8,%9},{%0,%1,%2,%3};"
        : "+f"(c[0]), "+f"(c[1]), "+f"(c[2]), "+f"(c[3])
        : "r"(a0), "r"(a1), "r"(a2), "r"(a3), "r"(b0), "r"(b1));
}

__device__ __forceinline__ float sigf(float x) { return 1.0f / (1.0f + expf(-x)); }

__device__ __forceinline__ void grid_bar() {
    __syncthreads();
    if (threadIdx.x == 0) {
        volatile unsigned* vg = &g_gen;
        unsigned my = *vg;
        __threadfence();
        unsigned prev = atomicAdd(&g_cnt, 1u);
        if (prev == NCTA2 - 1) {
            atomicExch(&g_cnt, 0u);
            __threadfence();
            atomicAdd(&g_gen, 1u);
        } else {
            while (*vg == my) { }
            __threadfence();
        }
    }
    __syncthreads();
}

// ==========================================================================
// Phase 1: Xg[t,b,n] = latent[t,b,:] @ W_ih^T + (b_ih + b_hh)
// Grid 8192 = 512 t-tiles x 16 n-tiles. CTA tile 128x128, K=512, tf32 mma.
// ==========================================================================
__global__ void __launch_bounds__(256) xgemm_kernel(
    const float* __restrict__ latent,   // [T*B, 512]
    const float* __restrict__ w_ih,     // [2048, 512]
    const float* __restrict__ b_ih,
    const float* __restrict__ b_hh)
{
    extern __shared__ float sm1[];
    float* bias_s = sm1;                       // 128
    float* A0 = sm1 + 128;                     // 128*36  = 4608
    float* B0 = A0 + 4608;                     // 8*128*4 = 4096
    float* A1 = B0 + 4096;
    float* B1 = A1 + 4608;

    const int tid  = threadIdx.x;
    const int nt   = blockIdx.x & 15;
    const int t    = blockIdx.x >> 4;
    const int n0   = nt * 128;
    const int lane = tid & 31, w = tid >> 5;
    const int mb   = (w & 3) * 32;             // warp M base (warp tile 32x64)
    const int nb   = (w >> 2) * 64;            // warp N base

    if (tid < 128) bias_s[tid] = b_ih[n0 + tid] + b_hh[n0 + tid];

    const float* __restrict__ Xrow = latent + (size_t)t * (B_ * 512);

    float c[2][8][4];
    #pragma unroll
    for (int i = 0; i < 2; i++)
        #pragma unroll
        for (int j = 0; j < 8; j++)
            #pragma unroll
            for (int k = 0; k < 4; k++) c[i][j][k] = 0.f;

    float4 ra[4], rb[4];

    auto LD = [&](int kt) {
        int k0 = kt * 32;
        #pragma unroll
        for (int i = 0; i < 4; i++) {
            int idx = tid + i * 256;
            int r = idx >> 3, kq = idx & 7;
            ra[i] = *reinterpret_cast<const float4*>(&Xrow[r * 512 + k0 + kq * 4]);
            rb[i] = *reinterpret_cast<const float4*>(&w_ih[(size_t)(n0 + r) * 512 + k0 + kq * 4]);
        }
    };
    auto ST = [&](float* A_s, float* B_s) {
        #pragma unroll
        for (int i = 0; i < 4; i++) {
            int idx = tid + i * 256;
            int r = idx >> 3, kq = idx & 7;
            float4 va = ra[i], vb = rb[i];
            va.x = f2tf_f(va.x); va.y = f2tf_f(va.y); va.z = f2tf_f(va.z); va.w = f2tf_f(va.w);
            vb.x = f2tf_f(vb.x); vb.y = f2tf_f(vb.y); vb.z = f2tf_f(vb.z); vb.w = f2tf_f(vb.w);
            *reinterpret_cast<float4*>(&A_s[r * 36 + kq * 4]) = va;           // [m][k] pad 36
            *reinterpret_cast<float4*>(&B_s[(kq * 128 + r) * 4]) = vb;        // [k/4][n][k%4]
        }
    };
    auto COMPUTE = [&](const float* A_s, const float* B_s) {
        const uint32_t* Au = reinterpret_cast<const uint32_t*>(A_s);
        const uint32_t* Bu = reinterpret_cast<const uint32_t*>(B_s);
        #pragma unroll
        for (int ks = 0; ks < 4; ++ks) {
            uint32_t a[2][4];
            #pragma unroll
            for (int mi = 0; mi < 2; mi++) {
                int r = mb + mi * 16 + (lane >> 2);
                int base = r * 36 + ks * 8 + (lane & 3);
                a[mi][0] = Au[base];          a[mi][1] = Au[base + 8 * 36];
                a[mi][2] = Au[base + 4];      a[mi][3] = Au[base + 8 * 36 + 4];
            }
            #pragma unroll
            for (int ni = 0; ni < 8; ++ni) {
                int n = nb + ni * 8 + (lane >> 2);
                int bidx = (ks * 2 * 128 + n) * 4 + (lane & 3);
                uint32_t b0 = Bu[bidx], b1 = Bu[bidx + 512];
                mma_tf32(c[0][ni], a[0][0], a[0][1], a[0][2], a[0][3], b0, b1);
                mma_tf32(c[1][ni], a[1][0], a[1][1], a[1][2], a[1][3], b0, b1);
            }
        }
    };

    LD(0); ST(A0, B0); __syncthreads();
    int buf = 0;
    #pragma unroll 1
    for (int kt = 0; kt < 16; ++kt) {
        if (kt < 15) LD(kt + 1);
        COMPUTE(buf ? A1 : A0, buf ? B1 : B0);
        if (kt < 15) {
            ST(buf ? A0 : A1, buf ? B0 : B1);
            __syncthreads();
            buf ^= 1;
        }
    }

    // epilogue: add bias, write Xg[t*128 + m][n0 + col]
    #pragma unroll
    for (int mi = 0; mi < 2; mi++) {
        #pragma unroll
        for (int ni = 0; ni < 8; ni++) {
            int r    = mb + mi * 16 + (lane >> 2);
            int colL = nb + ni * 8 + (lane & 3) * 2;
            float bv0 = bias_s[colL], bv1 = bias_s[colL + 1];
            size_t base = ((size_t)(t * 128 + r)) * G4 + n0 + colL;
            float2 v0; v0.x = c[mi][ni][0] + bv0; v0.y = c[mi][ni][1] + bv1;
            *reinterpret_cast<float2*>(&g_Xg[base]) = v0;
            float2 v1; v1.x = c[mi][ni][2] + bv0; v1.y = c[mi][ni][3] + bv1;
            *reinterpret_cast<float2*>(&g_Xg[base + (size_t)8 * G4]) = v1;
        }
    }
}

// ==========================================================================
// Phase 2: persistent recurrence. 128 CTAs x 128 threads, 1 grid bar / step.
// CTA (mg, cg): batch rows [mg*64,+64), hidden cols [cg*8,+8).
// Gate cols c in [0,32): c = q*8+jj -> n = q*512 + cg*8 + jj.
// W_hh slice resident in smem; h tile staged per step; C = h@W_hh^T via mma.
// smem: W_s 16384 | A_s 64x516 = 33024 | g_s 64x33 = 2112 floats (~201 KB)
// ==========================================================================
__global__ void __launch_bounds__(128) lstm_rec(
    const float*    __restrict__ h0,
    const float*    __restrict__ c0,
    const uint32_t* __restrict__ reset,    // [B,T]
    const uint32_t* __restrict__ clearm,   // [B,T]
    const float*    __restrict__ nstd,     // [B,T]
    const float*    __restrict__ noise,    // [T,B,H]
    const float*    __restrict__ w_hh,     // [2048,512]
    float*          __restrict__ out)
{
    extern __shared__ float sm2[];
    float* W_s = sm2;                  // 16384 floats
    float* A_s = sm2 + 16384;          // 33024 floats, [m][k] stride 516
    float* g_s = sm2 + 16384 + 33024;  // 2112 floats, [m][c] stride 33

    const int tid  = threadIdx.x;
    const int cb   = blockIdx.x;
    const int mg   = cb >> 6, cg = cb & 63;
    const int b0   = mg * 64, j0 = cg * 8;
    const int lane = tid & 31, w = tid >> 5;
    const int mb   = (w & 1) * 32;          // warp tile M=32
    const int cbs  = (w >> 1) * 16;         // warp tile C=16

    // ---- resident W fill (once): W_s[(k/4)*128 + c*4 + k%4] = tf32(w_hh[n(c)][k])
    for (int e = tid; e < 4096; e += 128) {
        int cc = e >> 7, kq = e & 127;
        int n = (cc >> 3) * 512 + j0 + (cc & 7);
        float4 v = *reinterpret_cast<const float4*>(&w_hh[(size_t)n * 512 + kq * 4]);
        v.x = f2tf_f(v.x); v.y = f2tf_f(v.y); v.z = f2tf_f(v.z); v.w = f2tf_f(v.w);
        *reinterpret_cast<float4*>(&W_s[(kq * 32 + cc) * 4]) = v;
    }

    // ---- init h/c with step-0 preprocessing; c lives in registers
    const int jE = tid & 7;
    float cst[4];
    #pragma unroll
    for (int ei = 0; ei < 4; ei++) {
        int m = (tid >> 3) + ei * 16;
        int b = b0 + m, j = j0 + jE;
        float h = h0[b * H_ + j];
        float cc = c0[b * H_ + j];
        bool msk = ((reset[b * T_] | clearm[b * T_]) != 0u);
        if (msk) { h = 0.f; cc = 0.f; }
        float nz = noise[(size_t)b * H_ + j] * nstd[b * T_];
        h += nz; cc += nz;
        g_h[0][b * H_ + j] = f2tf_f(h);   // tf32-round once at write
        cst[ei] = cc;
    }
    grid_bar();

    const int ar0 = (mb + (lane >> 2)) * 516 + (lane & 3);
    const int wb0 = (cbs + (lane >> 2)) * 4 + (lane & 3);
    const uint32_t* Au = reinterpret_cast<const uint32_t*>(A_s);
    const uint32_t* Wu = reinterpret_cast<const uint32_t*>(W_s);

    for (int t = 0; t < T_; ++t) {
        const float* __restrict__ hsrc = g_h[t & 1];

        // ---- stage h tile [64][512] (already tf32-rounded)
        #pragma unroll 8
        for (int i = 0; i < 64; i++) {
            int idx = tid + i * 128;
            int m = idx >> 7, kq = idx & 127;
            float4 v = *reinterpret_cast<const float4*>(&hsrc[(b0 + m) * 512 + kq * 4]);
            *reinterpret_cast<float4*>(&A_s[m * 516 + kq * 4]) = v;
        }
        __syncthreads();

        // ---- GEMM: 4 mma tiles per warp per kstep over 64 ksteps
        float acc[2][2][4];
        #pragma unroll
        for (int mi = 0; mi < 2; mi++)
            #pragma unroll
            for (int ci = 0; ci < 2; ci++)
                #pragma unroll
                for (int k = 0; k < 4; k++) acc[mi][ci][k] = 0.f;

        #pragma unroll 4
        for (int ks = 0; ks < 64; ++ks) {
            uint32_t a[2][4], bfr[2][2];
            #pragma unroll
            for (int mi = 0; mi < 2; mi++) {
                int base = ar0 + mi * 16 * 516 + ks * 8;
                a[mi][0] = Au[base];           a[mi][1] = Au[base + 8 * 516];
                a[mi][2] = Au[base + 4];       a[mi][3] = Au[base + 8 * 516 + 4];
            }
            #pragma unroll
            for (int ci = 0; ci < 2; ci++) {
                int base = wb0 + ks * 256 + ci * 32;
                bfr[ci][0] = Wu[base];
                bfr[ci][1] = Wu[base + 128];
            }
            #pragma unroll
            for (int mi = 0; mi < 2; mi++)
                #pragma unroll
                for (int ci = 0; ci < 2; ci++)
                    mma_tf32(acc[mi][ci], a[mi][0], a[mi][1], a[mi][2], a[mi][3],
                             bfr[ci][0], bfr[ci][1]);
        }

        // ---- spill gate frags to smem [m][c]
        #pragma unroll
        for (int mi = 0; mi < 2; mi++) {
            #pragma unroll
            for (int ci = 0; ci < 2; ci++) {
                int r  = mb + mi * 16 + (lane >> 2);
                int cc = cbs + ci * 8 + (lane & 3) * 2;
                g_s[r * 33 + cc]            = acc[mi][ci][0];
                g_s[r * 33 + cc + 1]        = acc[mi][ci][1];
                g_s[(r + 8) * 33 + cc]      = acc[mi][ci][2];
                g_s[(r + 8) * 33 + cc + 1]  = acc[mi][ci][3];
            }
        }
        __syncthreads();

        // ---- gates + state update + next-step preprocessing
        const float* __restrict__ Xg = g_Xg + (size_t)t * (B_ * G4);
        #pragma unroll
        for (int ei = 0; ei < 4; ei++) {
            int m = (tid >> 3) + ei * 16;
            int b = b0 + m, j = j0 + jE;
            size_t xb = (size_t)b * G4 + j;
            float gi = g_s[m * 33 + jE]      + Xg[xb];
            float gf = g_s[m * 33 + 8 + jE]  + Xg[xb + 512];
            float gg = g_s[m * 33 + 16 + jE] + Xg[xb + 1024];
            float go = g_s[m * 33 + 24 + jE] + Xg[xb + 1536];
            float i_ = sigf(gi);
            float f_ = sigf(gf);
            float g2 = tanhf(gg);
            float o_ = sigf(go);
            float cn = f_ * cst[ei] + i_ * g2;
            float hn = o_ * tanhf(cn);

            out[(size_t)t * (B_ * H_) + b * H_ + j] = hn;

            float hw, cw;
            if (t + 1 < T_) {
                bool msk = ((reset[b * T_ + t + 1] | clearm[b * T_ + t + 1]) != 0u);
                hw = msk ? 0.f : hn;
                cw = msk ? 0.f : cn;
                float nz = noise[(size_t)(t + 1) * (B_ * H_) + b * H_ + j]
                         * nstd[b * T_ + t + 1];
                hw += nz; cw += nz;
            } else {
                hw = hn; cw = cn;
                out[(size_t)T_ * (B_ * H_)           + b * H_ + j] = hn;   // hN
                out[(size_t)T_ * (B_ * H_) + B_ * H_ + b * H_ + j] = cn;   // cN
            }
            g_h[(t + 1) & 1][b * H_ + j] = f2tf_f(hw);
            cst[ei] = cw;
        }

        grid_bar();
    }
}

// ==========================================================================
extern "C" void kernel_launch(void* const* d_in, const int* in_sizes, int n_in,
                              void* d_out, int out_size) {
    (void)in_sizes; (void)n_in; (void)out_size;
    const float*    latent = (const float*)d_in[0];
    const float*    h0     = (const float*)d_in[1];
    const float*    c0     = (const float*)d_in[2];
    const uint32_t* reset  = (const uint32_t*)d_in[3];
    const uint32_t* clearm = (const uint32_t*)d_in[4];
    const float*    nstd   = (const float*)d_in[5];
    const float*    noise  = (const float*)d_in[6];
    const float*    w_ih   = (const float*)d_in[7];
    const float*    w_hh   = (const float*)d_in[8];
    const float*    b_ih   = (const float*)d_in[9];
    const float*    b_hh   = (const float*)d_in[10];
    float* out = (float*)d_out;

    const int smem1 = (128 + 2 * (4608 + 4096)) * 4;                 // 70144 B
    const int smem2 = (16384 + 33024 + 2112) * 4;                    // 206080 B
    cudaFuncSetAttribute(xgemm_kernel, cudaFuncAttributeMaxDynamicSharedMemorySize, smem1);
    cudaFuncSetAttribute(lstm_rec,     cudaFuncAttributeMaxDynamicSharedMemorySize, smem2);

    xgemm_kernel<<<512 * 16, 256, smem1>>>(latent, w_ih, b_ih, b_hh);
    lstm_rec<<<NCTA2, 128, smem2>>>(h0, c0, reset, clearm, nstd, noise, w_hh, out);
}

// round 3
// speedup vs baseline: 4.8096x; 2.7111x over previous
#include <cuda_runtime.h>
#include <cuda_fp16.h>
#include <cstdint>
#include <cstddef>

#define T_   512
#define B_   128
#define H_   512
#define G4   2048

// ---------------- scratch (device globals; no allocation) ----------------
__device__ float    g_Xg[(size_t)T_ * B_ * G4];   // 512 MB: x@W_ih^T + b_ih + b_hh
__device__ __half   g_h2[2][B_ * H_];             // double-buffered fp16 h
__device__ unsigned g_cnt2[8 * 32];               // per-group barrier (padded lines)
__device__ unsigned g_gen2[8 * 32];

// ---------------- helpers ----------------
__device__ __forceinline__ void mma_f16(float c[4], const uint32_t a[4],
                                        uint32_t b0, uint32_t b1) {
    asm volatile(
        "mma.sync.aligned.m16n8k16.row.col.f32.f16.f16.f32 "
        "{%0,%1,%2,%3},{%4,%5,%6,%7},{%8,%9},{%0,%1,%2,%3};"
        : "+f"(c[0]), "+f"(c[1]), "+f"(c[2]), "+f"(c[3])
        : "r"(a[0]), "r"(a[1]), "r"(a[2]), "r"(a[3]), "r"(b0), "r"(b1));
}

__device__ __forceinline__ float sigf(float x) { return 1.0f / (1.0f + expf(-x)); }

__device__ __forceinline__ uint32_t h2u(float x, float y) {
    __half2 h = __floats2half2_rn(x, y);
    return *reinterpret_cast<uint32_t*>(&h);
}

// pair-index interleave so (b0,b1) are adjacent 32-bit words -> LDS.64
__device__ __forceinline__ int pidx(int p) { return (p & 3) * 2 + (p >> 2); }

// 16-CTA group barrier (groups are independent)
__device__ __forceinline__ void group_bar(int mg) {
    __syncthreads();
    if (threadIdx.x == 0) {
        volatile unsigned* vg = &g_gen2[mg * 32];
        unsigned my = *vg;
        __threadfence();
        unsigned prev = atomicAdd(&g_cnt2[mg * 32], 1u);
        if (prev == 15u) {
            atomicExch(&g_cnt2[mg * 32], 0u);
            __threadfence();
            atomicAdd(&g_gen2[mg * 32], 1u);
        } else {
            while (*vg == my) { }
            __threadfence();
        }
    }
    __syncthreads();
}

// ==========================================================================
// Phase 1: Xg[t,b,n] = latent[t,b,:] @ W_ih^T + (b_ih + b_hh)   (fp16 mma)
// Grid 8192 = 512 t x 16 n-tiles. CTA tile 128x128, K=512, k-stage=32.
// ==========================================================================
__global__ void __launch_bounds__(256) xgemm_fp16(
    const float* __restrict__ latent,   // [T*B, 512]
    const float* __restrict__ w_ih,     // [2048, 512]
    const float* __restrict__ b_ih,
    const float* __restrict__ b_hh)
{
    extern __shared__ __align__(16) unsigned char sm[];
    float*    bias_s = (float*)sm;                         // 512 B
    __half*   A0 = (__half*)(sm + 512);                    // 128*40 fp16 = 10240 B
    __half*   A1 = A0 + 5120;
    uint32_t* B0 = (uint32_t*)(sm + 512 + 20480);          // 2*128*8 u32 = 8192 B
    uint32_t* B1 = B0 + 2048;

    const int tid  = threadIdx.x;
    const int nt   = blockIdx.x & 15;
    const int tt   = blockIdx.x >> 4;
    const int n0   = nt * 128;
    const int lane = tid & 31, w = tid >> 5;
    const int mb   = (w & 3) * 32;              // warp tile 32x64
    const int nb2  = (w >> 2) * 64;

    if (tid < 128) bias_s[tid] = b_ih[n0 + tid] + b_hh[n0 + tid];

    const float* __restrict__ Xrow = latent + (size_t)tt * (128 * 512);

    float c[2][8][4];
    #pragma unroll
    for (int i = 0; i < 2; i++)
        #pragma unroll
        for (int j = 0; j < 8; j++)
            #pragma unroll
            for (int k = 0; k < 4; k++) c[i][j][k] = 0.f;

    float4 ra[4], rb[4];

    auto LD = [&](int kt) {
        int k0 = kt * 32;
        #pragma unroll
        for (int i = 0; i < 4; i++) {
            int idx = tid + i * 256;
            int r = idx >> 3, c4 = idx & 7;
            ra[i] = *reinterpret_cast<const float4*>(&Xrow[r * 512 + k0 + c4 * 4]);
            rb[i] = *reinterpret_cast<const float4*>(&w_ih[(size_t)(n0 + r) * 512 + k0 + c4 * 4]);
        }
    };
    auto ST = [&](__half* As, uint32_t* Bs) {
        #pragma unroll
        for (int i = 0; i < 4; i++) {
            int idx = tid + i * 256;
            int r = idx >> 3, c4 = idx & 7;
            uint2 av;
            av.x = h2u(ra[i].x, ra[i].y);
            av.y = h2u(ra[i].z, ra[i].w);
            *reinterpret_cast<uint2*>(&As[r * 40 + c4 * 4]) = av;
            int ks = c4 >> 2, pp = (c4 & 3) * 2;
            Bs[(ks * 128 + r) * 8 + pidx(pp)]     = h2u(rb[i].x, rb[i].y);
            Bs[(ks * 128 + r) * 8 + pidx(pp + 1)] = h2u(rb[i].z, rb[i].w);
        }
    };
    auto COMPUTE = [&](const __half* As, const uint32_t* Bs) {
        const uint32_t* Au = reinterpret_cast<const uint32_t*>(As);
        #pragma unroll
        for (int ks = 0; ks < 2; ++ks) {
            uint32_t a[2][4];
            #pragma unroll
            for (int mi = 0; mi < 2; mi++) {
                int base = (mb + mi * 16 + (lane >> 2)) * 20 + ks * 8 + (lane & 3);
                a[mi][0] = Au[base];       a[mi][1] = Au[base + 160];
                a[mi][2] = Au[base + 4];   a[mi][3] = Au[base + 164];
            }
            #pragma unroll
            for (int ni = 0; ni < 8; ++ni) {
                int n = nb2 + ni * 8 + (lane >> 2);
                uint2 bv = *reinterpret_cast<const uint2*>(&Bs[(ks * 128 + n) * 8 + (lane & 3) * 2]);
                mma_f16(c[0][ni], a[0], bv.x, bv.y);
                mma_f16(c[1][ni], a[1], bv.x, bv.y);
            }
        }
    };

    LD(0); ST(A0, B0); __syncthreads();
    int buf = 0;
    #pragma unroll 1
    for (int kt = 0; kt < 16; ++kt) {
        if (kt < 15) LD(kt + 1);
        COMPUTE(buf ? A1 : A0, buf ? B1 : B0);
        if (kt < 15) {
            ST(buf ? A0 : A1, buf ? B0 : B1);
            __syncthreads();
            buf ^= 1;
        }
    }

    #pragma unroll
    for (int mi = 0; mi < 2; mi++) {
        #pragma unroll
        for (int ni = 0; ni < 8; ni++) {
            int r    = mb + mi * 16 + (lane >> 2);
            int colL = nb2 + ni * 8 + (lane & 3) * 2;
            float bv0 = bias_s[colL], bv1 = bias_s[colL + 1];
            size_t base = ((size_t)(tt * 128 + r)) * G4 + n0 + colL;
            float2 v0; v0.x = c[mi][ni][0] + bv0; v0.y = c[mi][ni][1] + bv1;
            *reinterpret_cast<float2*>(&g_Xg[base]) = v0;
            float2 v1; v1.x = c[mi][ni][2] + bv0; v1.y = c[mi][ni][3] + bv1;
            *reinterpret_cast<float2*>(&g_Xg[base + (size_t)8 * G4]) = v1;
        }
    }
}

// ==========================================================================
// Phase 2: persistent recurrence, fp16 mma.
// 128 CTAs x 256 thr. CTA (mg,cg): rows [mg*16,+16), hidden cols [cg*32,+32)
// -> 128 gate cols (c = q*32+jj, n = q*512 + cg*32 + jj). W fp16 resident
// in smem (128 KB). 8 independent 16-CTA barriers (one per row group).
// ==========================================================================
__global__ void __launch_bounds__(256) lstm_rec16(
    const float*    __restrict__ h0,
    const float*    __restrict__ c0,
    const uint32_t* __restrict__ reset,    // [B,T]
    const uint32_t* __restrict__ clearm,   // [B,T]
    const float*    __restrict__ nstd,     // [B,T]
    const float*    __restrict__ noise,    // [T,B,H]
    const float*    __restrict__ w_hh,     // [2048,512]
    float*          __restrict__ out)
{
    extern __shared__ __align__(16) unsigned char sm[];
    uint32_t* W_s = (uint32_t*)sm;                         // 32 ks *128 c *8 = 131072 B
    __half*   A_s = (__half*)(sm + 131072);                // 16 x 520 fp16 = 16640 B
    float*    gsm = (float*)(sm + 131072 + 16640);         // 16 x 132 f32 = 8448 B

    const int tid  = threadIdx.x;
    const int cb   = blockIdx.x;
    const int mg   = cb >> 4, cg = cb & 15;
    const int b0   = mg * 16, j0 = cg * 32;
    const int lane = tid & 31, w = tid >> 5;

    // ---- W fill (once): W_s[(ks*128 + c)*8 + pidx(p)] = half2(w_hh[n][k..k+1])
    for (int e = tid; e < 128 * 256; e += 256) {
        int cc = e >> 8, pr = e & 255;
        int ks = pr >> 3, p = pr & 7;
        int k = ks * 16 + p * 2;
        int n = (cc >> 5) * 512 + j0 + (cc & 31);
        float2 wv = *reinterpret_cast<const float2*>(&w_hh[(size_t)n * 512 + k]);
        W_s[(ks * 128 + cc) * 8 + pidx(p)] = h2u(wv.x, wv.y);
    }

    // ---- init owned h/c patch with step-0 preprocessing; c stays in regs
    const int row = tid >> 4;            // 0..15
    const int jj  = (tid & 15) * 2;      // 0..30
    const int b   = b0 + row, j = j0 + jj;
    float cst0, cst1;
    {
        float hA = h0[b * H_ + j],     cA = c0[b * H_ + j];
        float hB = h0[b * H_ + j + 1], cB = c0[b * H_ + j + 1];
        bool msk = ((reset[b * T_] | clearm[b * T_]) != 0u);
        if (msk) { hA = cA = hB = cB = 0.f; }
        float s = nstd[b * T_];
        float2 nz = *reinterpret_cast<const float2*>(&noise[(size_t)b * H_ + j]);
        hA += nz.x * s; cA += nz.x * s;
        hB += nz.y * s; cB += nz.y * s;
        *reinterpret_cast<uint32_t*>(&g_h2[0][b * H_ + j]) = h2u(hA, hB);
        cst0 = cA; cst1 = cB;
    }
    group_bar(mg);

    const int abase = (lane >> 2) * 260 + (lane & 3);
    const int nb    = w * 16;
    uint32_t* Au = reinterpret_cast<uint32_t*>(A_s);

    for (int t = 0; t < T_; ++t) {
        const __half* __restrict__ hsrc = g_h2[t & 1];

        // ---- stage h tile [16][512] fp16 (16 KB): 4 x uint4 per thread
        #pragma unroll
        for (int i = 0; i < 4; i++) {
            int idx = tid + i * 256;
            int r = idx >> 6, c8 = idx & 63;
            uint4 v = *reinterpret_cast<const uint4*>(&hsrc[(b0 + r) * H_ + c8 * 8]);
            *reinterpret_cast<uint4*>(&A_s[r * 520 + c8 * 8]) = v;
        }
        __syncthreads();

        // ---- GEMM: warp tile 16 x 16 (2 n-tiles), 32 ksteps
        float acc[2][4];
        #pragma unroll
        for (int ni = 0; ni < 2; ni++)
            #pragma unroll
            for (int k = 0; k < 4; k++) acc[ni][k] = 0.f;

        #pragma unroll 4
        for (int ks = 0; ks < 32; ++ks) {
            uint32_t a[4];
            int ab = abase + ks * 8;
            a[0] = Au[ab];        a[1] = Au[ab + 2080];
            a[2] = Au[ab + 4];    a[3] = Au[ab + 2084];
            #pragma unroll
            for (int ni = 0; ni < 2; ni++) {
                int n = nb + ni * 8 + (lane >> 2);
                uint2 bv = *reinterpret_cast<const uint2*>(
                    &W_s[(ks * 128 + n) * 8 + (lane & 3) * 2]);
                mma_f16(acc[ni], a, bv.x, bv.y);
            }
        }

        // ---- spill gate fragments to gsm[row][c]
        #pragma unroll
        for (int ni = 0; ni < 2; ni++) {
            int r  = lane >> 2;
            int cc = nb + ni * 8 + (lane & 3) * 2;
            float2 v0; v0.x = acc[ni][0]; v0.y = acc[ni][1];
            float2 v1; v1.x = acc[ni][2]; v1.y = acc[ni][3];
            *reinterpret_cast<float2*>(&gsm[r * 132 + cc])       = v0;
            *reinterpret_cast<float2*>(&gsm[(r + 8) * 132 + cc]) = v1;
        }
        __syncthreads();

        // ---- gates + state update + next-step preprocessing (2 elems/thread)
        {
            const float* __restrict__ Xgp = g_Xg + ((size_t)t * B_ + b) * G4;
            float2 gi = *reinterpret_cast<const float2*>(&gsm[row * 132 + jj]);
            float2 gf = *reinterpret_cast<const float2*>(&gsm[row * 132 + 32 + jj]);
            float2 gg = *reinterpret_cast<const float2*>(&gsm[row * 132 + 64 + jj]);
            float2 go = *reinterpret_cast<const float2*>(&gsm[row * 132 + 96 + jj]);
            float2 xi = *reinterpret_cast<const float2*>(&Xgp[j]);
            float2 xf = *reinterpret_cast<const float2*>(&Xgp[512 + j]);
            float2 xg = *reinterpret_cast<const float2*>(&Xgp[1024 + j]);
            float2 xo = *reinterpret_cast<const float2*>(&Xgp[1536 + j]);

            float iA = sigf(gi.x + xi.x), iB = sigf(gi.y + xi.y);
            float fA = sigf(gf.x + xf.x), fB = sigf(gf.y + xf.y);
            float gA = tanhf(gg.x + xg.x), gB = tanhf(gg.y + xg.y);
            float oA = sigf(go.x + xo.x), oB = sigf(go.y + xo.y);

            float cnA = fA * cst0 + iA * gA;
            float cnB = fB * cst1 + iB * gB;
            float hnA = oA * tanhf(cnA);
            float hnB = oB * tanhf(cnB);

            float2 ho; ho.x = hnA; ho.y = hnB;
            *reinterpret_cast<float2*>(&out[((size_t)t * B_ + b) * H_ + j]) = ho;

            float hwA, hwB, cwA, cwB;
            if (t + 1 < T_) {
                bool msk = ((reset[b * T_ + t + 1] | clearm[b * T_ + t + 1]) != 0u);
                hwA = msk ? 0.f : hnA; cwA = msk ? 0.f : cnA;
                hwB = msk ? 0.f : hnB; cwB = msk ? 0.f : cnB;
                float s = nstd[b * T_ + t + 1];
                float2 nz = *reinterpret_cast<const float2*>(
                    &noise[((size_t)(t + 1) * B_ + b) * H_ + j]);
                hwA += nz.x * s; cwA += nz.x * s;
                hwB += nz.y * s; cwB += nz.y * s;
            } else {
                hwA = hnA; cwA = cnA; hwB = hnB; cwB = cnB;
                float2 hv; hv.x = hnA; hv.y = hnB;
                float2 cv; cv.x = cnA; cv.y = cnB;
                *reinterpret_cast<float2*>(&out[(size_t)T_ * (B_ * H_) + b * H_ + j]) = hv;
                *reinterpret_cast<float2*>(&out[(size_t)T_ * (B_ * H_) + B_ * H_ + b * H_ + j]) = cv;
            }
            *reinterpret_cast<uint32_t*>(&g_h2[(t + 1) & 1][b * H_ + j]) = h2u(hwA, hwB);
            cst0 = cwA; cst1 = cwB;
        }

        group_bar(mg);
    }
}

// ==========================================================================
extern "C" void kernel_launch(void* const* d_in, const int* in_sizes, int n_in,
                              void* d_out, int out_size) {
    (void)in_sizes; (void)n_in; (void)out_size;
    const float*    latent = (const float*)d_in[0];
    const float*    h0     = (const float*)d_in[1];
    const float*    c0     = (const float*)d_in[2];
    const uint32_t* reset  = (const uint32_t*)d_in[3];
    const uint32_t* clearm = (const uint32_t*)d_in[4];
    const float*    nstd   = (const float*)d_in[5];
    const float*    noise  = (const float*)d_in[6];
    const float*    w_ih   = (const float*)d_in[7];
    const float*    w_hh   = (const float*)d_in[8];
    const float*    b_ih   = (const float*)d_in[9];
    const float*    b_hh   = (const float*)d_in[10];
    float* out = (float*)d_out;

    const int smem1 = 512 + 20480 + 16384;            // 37376 B
    const int smem2 = 131072 + 16640 + 8448;          // 156160 B
    cudaFuncSetAttribute(xgemm_fp16, cudaFuncAttributeMaxDynamicSharedMemorySize, smem1);
    cudaFuncSetAttribute(lstm_rec16, cudaFuncAttributeMaxDynamicSharedMemorySize, smem2);

    xgemm_fp16<<<512 * 16, 256, smem1>>>(latent, w_ih, b_ih, b_hh);
    lstm_rec16<<<128, 256, smem2>>>(h0, c0, reset, clearm, nstd, noise, w_hh, out);
}

// round 4
// speedup vs baseline: 7.0138x; 1.4583x over previous
#include <cuda_runtime.h>
#include <cuda_fp16.h>
#include <cstdint>
#include <cstddef>

#define T_   512
#define B_   128
#define H_   512
#define G4   2048
#define NG   16      // CTAs per row-group (phase 2)

// ---------------- scratch (device globals; no allocation) ----------------
__device__ float    g_Xg[(size_t)T_ * B_ * G4];   // 512 MB: x@W_ih^T + b_ih + b_hh
__device__ __half   g_h2[2][B_ * H_];             // double-buffered fp16 h
__device__ unsigned g_bar[8 * 1024];              // per-group step counters (self-zeroing)

// ---------------- helpers ----------------
__device__ __forceinline__ void mma_f16(float c[4], const uint32_t a[4],
                                        uint32_t b0, uint32_t b1) {
    asm volatile(
        "mma.sync.aligned.m16n8k16.row.col.f32.f16.f16.f32 "
        "{%0,%1,%2,%3},{%4,%5,%6,%7},{%8,%9},{%0,%1,%2,%3};"
        : "+f"(c[0]), "+f"(c[1]), "+f"(c[2]), "+f"(c[3])
        : "r"(a[0]), "r"(a[1]), "r"(a[2]), "r"(a[3]), "r"(b0), "r"(b1));
}
__device__ __forceinline__ void ldsm4(uint32_t r[4], uint32_t saddr) {
    asm volatile("ldmatrix.sync.aligned.m8n8.x4.shared.b16 {%0,%1,%2,%3},[%4];"
        : "=r"(r[0]), "=r"(r[1]), "=r"(r[2]), "=r"(r[3]) : "r"(saddr));
}
__device__ __forceinline__ void cp16(uint32_t sdst, const void* gsrc) {
    asm volatile("cp.async.ca.shared.global [%0],[%1],16;" :: "r"(sdst), "l"(gsrc));
}
__device__ __forceinline__ uint32_t h2u(float x, float y) {
    __half2 h = __floats2half2_rn(x, y);
    return *reinterpret_cast<uint32_t*>(&h);
}
__device__ __forceinline__ int pidx(int p) { return (p & 3) * 2 + (p >> 2); }

__device__ __forceinline__ float sigf(float x) {
    return __fdividef(1.0f, 1.0f + __expf(-x));
}
__device__ __forceinline__ float tanhfast(float x) {
    return 1.0f - 2.0f * __fdividef(1.0f, __expf(2.0f * x) + 1.0f);
}

// ==========================================================================
// Phase 1: Xg[t,b,n] = latent[t,b,:] @ W_ih^T + (b_ih + b_hh)   (fp16 mma)
// ==========================================================================
__global__ void __launch_bounds__(256) xgemm_fp16(
    const float* __restrict__ latent,   // [T*B, 512]
    const float* __restrict__ w_ih,     // [2048, 512]
    const float* __restrict__ b_ih,
    const float* __restrict__ b_hh)
{
    extern __shared__ __align__(16) unsigned char sm[];
    float*    bias_s = (float*)sm;
    __half*   A0 = (__half*)(sm + 512);
    __half*   A1 = A0 + 5120;
    uint32_t* B0 = (uint32_t*)(sm + 512 + 20480);
    uint32_t* B1 = B0 + 2048;

    const int tid  = threadIdx.x;
    const int nt   = blockIdx.x & 15;
    const int tt   = blockIdx.x >> 4;
    const int n0   = nt * 128;
    const int lane = tid & 31, w = tid >> 5;
    const int mb   = (w & 3) * 32;
    const int nb2  = (w >> 2) * 64;

    if (tid < 128) bias_s[tid] = b_ih[n0 + tid] + b_hh[n0 + tid];

    const float* __restrict__ Xrow = latent + (size_t)tt * (128 * 512);

    float c[2][8][4];
    #pragma unroll
    for (int i = 0; i < 2; i++)
        #pragma unroll
        for (int j = 0; j < 8; j++)
            #pragma unroll
            for (int k = 0; k < 4; k++) c[i][j][k] = 0.f;

    float4 ra[4], rb[4];

    auto LD = [&](int kt) {
        int k0 = kt * 32;
        #pragma unroll
        for (int i = 0; i < 4; i++) {
            int idx = tid + i * 256;
            int r = idx >> 3, c4 = idx & 7;
            ra[i] = *reinterpret_cast<const float4*>(&Xrow[r * 512 + k0 + c4 * 4]);
            rb[i] = *reinterpret_cast<const float4*>(&w_ih[(size_t)(n0 + r) * 512 + k0 + c4 * 4]);
        }
    };
    auto ST = [&](__half* As, uint32_t* Bs) {
        #pragma unroll
        for (int i = 0; i < 4; i++) {
            int idx = tid + i * 256;
            int r = idx >> 3, c4 = idx & 7;
            uint2 av;
            av.x = h2u(ra[i].x, ra[i].y);
            av.y = h2u(ra[i].z, ra[i].w);
            *reinterpret_cast<uint2*>(&As[r * 40 + c4 * 4]) = av;
            int ks = c4 >> 2, pp = (c4 & 3) * 2;
            Bs[(ks * 128 + r) * 8 + pidx(pp)]     = h2u(rb[i].x, rb[i].y);
            Bs[(ks * 128 + r) * 8 + pidx(pp + 1)] = h2u(rb[i].z, rb[i].w);
        }
    };
    auto COMPUTE = [&](const __half* As, const uint32_t* Bs) {
        const uint32_t* Au = reinterpret_cast<const uint32_t*>(As);
        #pragma unroll
        for (int ks = 0; ks < 2; ++ks) {
            uint32_t a[2][4];
            #pragma unroll
            for (int mi = 0; mi < 2; mi++) {
                int base = (mb + mi * 16 + (lane >> 2)) * 20 + ks * 8 + (lane & 3);
                a[mi][0] = Au[base];       a[mi][1] = Au[base + 160];
                a[mi][2] = Au[base + 4];   a[mi][3] = Au[base + 164];
            }
            #pragma unroll
            for (int ni = 0; ni < 8; ++ni) {
                int n = nb2 + ni * 8 + (lane >> 2);
                uint2 bv = *reinterpret_cast<const uint2*>(&Bs[(ks * 128 + n) * 8 + (lane & 3) * 2]);
                mma_f16(c[0][ni], a[0], bv.x, bv.y);
                mma_f16(c[1][ni], a[1], bv.x, bv.y);
            }
        }
    };

    LD(0); ST(A0, B0); __syncthreads();
    int buf = 0;
    #pragma unroll 1
    for (int kt = 0; kt < 16; ++kt) {
        if (kt < 15) LD(kt + 1);
        COMPUTE(buf ? A1 : A0, buf ? B1 : B0);
        if (kt < 15) {
            ST(buf ? A0 : A1, buf ? B0 : B1);
            __syncthreads();
            buf ^= 1;
        }
    }

    #pragma unroll
    for (int mi = 0; mi < 2; mi++) {
        #pragma unroll
        for (int ni = 0; ni < 8; ni++) {
            int r    = mb + mi * 16 + (lane >> 2);
            int colL = nb2 + ni * 8 + (lane & 3) * 2;
            float bv0 = bias_s[colL], bv1 = bias_s[colL + 1];
            size_t base = ((size_t)(tt * 128 + r)) * G4 + n0 + colL;
            float2 v0; v0.x = c[mi][ni][0] + bv0; v0.y = c[mi][ni][1] + bv1;
            *reinterpret_cast<float2*>(&g_Xg[base]) = v0;
            float2 v1; v1.x = c[mi][ni][2] + bv0; v1.y = c[mi][ni][3] + bv1;
            *reinterpret_cast<float2*>(&g_Xg[base + (size_t)8 * G4]) = v1;
        }
    }
}

// ==========================================================================
// Phase 2: persistent recurrence, fp16 mma + ldmatrix + release/acquire sync.
// 128 CTAs x 256 thr. CTA (mg,cg): rows [mg*16,+16), hidden cols [cg*32,+32)
// Per step: prefetch Xg/noise -> wait counter[t] -> cp.async h tile ->
// GEMM (LDSM x4 A/B, 2 mma per kslice per warp) -> spill -> epilogue ->
// store h[t+1] -> red.release counter[t+1]. Counters self-zero (t-1 at step t).
// smem: W_s 196608 | A_s 16x520 fp16 = 16640 | gsm 16x132 f32 = 8448  (221696 B)
// ==========================================================================
__global__ void __launch_bounds__(256, 1) lstm_rec16(
    const float*    __restrict__ h0,
    const float*    __restrict__ c0,
    const uint32_t* __restrict__ reset,    // [B,T]
    const uint32_t* __restrict__ clearm,   // [B,T]
    const float*    __restrict__ nstd,     // [B,T]
    const float*    __restrict__ noise,    // [T,B,H]
    const float*    __restrict__ w_hh,     // [2048,512]
    float*          __restrict__ out)
{
    extern __shared__ __align__(16) unsigned char sm[];
    __half* W_s = (__half*)sm;                       // 196608 B, atom stride 48 B
    __half* A_s = (__half*)(sm + 196608);            // 16 x 520 halves
    float*  gsm = (float*)(sm + 196608 + 16640);     // 16 x 132 f32

    const int tid  = threadIdx.x;
    const int cb   = blockIdx.x;
    const int mg   = cb >> 4, cg = cb & 15;
    const int b0   = mg * 16, j0 = cg * 32;
    const int lane = tid & 31, w = tid >> 5;
    const int nb   = w * 16;                         // warp gate-col base (0..112)

    unsigned* bar = &g_bar[mg * 1024];

    // ---- W_s fill (once): atom (ks, c) = 16 halves of w_hh[n(c)][ks*16..+16)
    for (int e = tid; e < 4096; e += 256) {
        int ks = e >> 7, c = e & 127;
        int n = (c >> 5) * 512 + j0 + (c & 31);
        const float4* wp = reinterpret_cast<const float4*>(&w_hh[(size_t)n * 512 + ks * 16]);
        float4 w0 = wp[0], w1 = wp[1], w2 = wp[2], w3 = wp[3];
        uint4 lo, hi;
        lo.x = h2u(w0.x, w0.y); lo.y = h2u(w0.z, w0.w);
        lo.z = h2u(w1.x, w1.y); lo.w = h2u(w1.z, w1.w);
        hi.x = h2u(w2.x, w2.y); hi.y = h2u(w2.z, w2.w);
        hi.z = h2u(w3.x, w3.y); hi.w = h2u(w3.z, w3.w);
        char* base = (char*)W_s + (size_t)(ks * 128 + c) * 48;
        *reinterpret_cast<uint4*>(base)      = lo;
        *reinterpret_cast<uint4*>(base + 16) = hi;
    }

    // ---- init owned h/c patch with step-0 preprocessing; c stays in regs
    const int row = tid >> 4;            // 0..15
    const int jj  = (tid & 15) * 2;      // 0..30
    const int b   = b0 + row, j = j0 + jj;
    float cst0, cst1;
    {
        float hA = h0[b * H_ + j],     cA = c0[b * H_ + j];
        float hB = h0[b * H_ + j + 1], cB = c0[b * H_ + j + 1];
        bool msk = ((reset[b * T_] | clearm[b * T_]) != 0u);
        if (msk) { hA = cA = hB = cB = 0.f; }
        float s = nstd[b * T_];
        float2 nz = *reinterpret_cast<const float2*>(&noise[(size_t)b * H_ + j]);
        hA += nz.x * s; cA += nz.x * s;
        hB += nz.y * s; cB += nz.y * s;
        *reinterpret_cast<uint32_t*>(&g_h2[0][b * H_ + j]) = h2u(hA, hB);
        cst0 = cA; cst1 = cB;
    }
    __syncthreads();
    if (tid == 0)
        asm volatile("red.release.gpu.global.add.u32 [%0], %1;" :: "l"(&bar[0]), "r"(1u) : "memory");

    // ---- per-lane LDSM addresses
    const uint32_t Ws_sa = (uint32_t)__cvta_generic_to_shared(W_s);
    const uint32_t As_sa = (uint32_t)__cvta_generic_to_shared(A_s);
    {
    }
    const int mq   = lane >> 3, rl = lane & 7;
    const int rowL = (mq & 1) * 8 + rl;
    const int koff = (mq >> 1) * 8;
    const uint32_t aAddr0 = As_sa + rowL * 1040 + koff * 2;              // + ks*32
    const uint32_t bAddr0 = Ws_sa + (nb + rowL) * 48 + koff * 2;         // + ks*6144

    // staging map: 4 x 16B per thread
    const int stR  = tid >> 6;           // row step base within 4-iter loop
    const int stC  = tid & 63;

    for (int t = 0; t < T_; ++t) {
        // ---- prefetch (independent of h[t]) ----
        const float* __restrict__ Xgp = g_Xg + ((size_t)t * B_ + b) * G4;
        float2 xi = *reinterpret_cast<const float2*>(&Xgp[j]);
        float2 xf = *reinterpret_cast<const float2*>(&Xgp[512 + j]);
        float2 xg = *reinterpret_cast<const float2*>(&Xgp[1024 + j]);
        float2 xo = *reinterpret_cast<const float2*>(&Xgp[1536 + j]);
        unsigned mskN = 0; float sN = 0.f; float2 nzN; nzN.x = 0.f; nzN.y = 0.f;
        if (t + 1 < T_) {
            mskN = reset[b * T_ + t + 1] | clearm[b * T_ + t + 1];
            sN   = nstd[b * T_ + t + 1];
            nzN  = *reinterpret_cast<const float2*>(&noise[((size_t)(t + 1) * B_ + b) * H_ + j]);
        }

        // ---- wait for h[t] ----
        if (tid == 0) {
            unsigned v;
            do {
                asm volatile("ld.acquire.gpu.global.u32 %0, [%1];"
                             : "=r"(v) : "l"(&bar[t]) : "memory");
            } while (v < NG);
            if (cg == 0 && t >= 1) bar[t - 1] = 0;   // safe: all passed wait[t]
        }
        __syncthreads();

        // ---- stage h tile [16][512] fp16 via cp.async ----
        const __half* __restrict__ hsrc = g_h2[t & 1];
        #pragma unroll
        for (int i = 0; i < 4; i++) {
            int r = stR + i * 4;
            cp16(As_sa + r * 1040 + stC * 16, &hsrc[(b0 + r) * H_ + stC * 8]);
        }
        asm volatile("cp.async.commit_group;");
        asm volatile("cp.async.wait_group 0;");
        __syncthreads();

        // ---- GEMM: 32 ksteps, per warp: LDSM.x4 A + LDSM.x4 B + 2 mma ----
        float acc0[4] = {0.f, 0.f, 0.f, 0.f};
        float acc1[4] = {0.f, 0.f, 0.f, 0.f};
        #pragma unroll 8
        for (int ks = 0; ks < 32; ++ks) {
            uint32_t a[4], bb[4];
            ldsm4(a,  aAddr0 + ks * 32);
            ldsm4(bb, bAddr0 + ks * 6144);
            mma_f16(acc0, a, bb[0], bb[2]);
            mma_f16(acc1, a, bb[1], bb[3]);
        }

        // ---- spill gate fragments to gsm[row][c] ----
        {
            int r  = lane >> 2;
            int cc = nb + (lane & 3) * 2;
            float2 v;
            v.x = acc0[0]; v.y = acc0[1];
            *reinterpret_cast<float2*>(&gsm[r * 132 + cc]) = v;
            v.x = acc0[2]; v.y = acc0[3];
            *reinterpret_cast<float2*>(&gsm[(r + 8) * 132 + cc]) = v;
            v.x = acc1[0]; v.y = acc1[1];
            *reinterpret_cast<float2*>(&gsm[r * 132 + cc + 8]) = v;
            v.x = acc1[2]; v.y = acc1[3];
            *reinterpret_cast<float2*>(&gsm[(r + 8) * 132 + cc + 8]) = v;
        }
        __syncthreads();

        // ---- gates + state update + next-step preprocessing ----
        {
            float2 gi = *reinterpret_cast<const float2*>(&gsm[row * 132 + jj]);
            float2 gf = *reinterpret_cast<const float2*>(&gsm[row * 132 + 32 + jj]);
            float2 gg = *reinterpret_cast<const float2*>(&gsm[row * 132 + 64 + jj]);
            float2 go = *reinterpret_cast<const float2*>(&gsm[row * 132 + 96 + jj]);

            float iA = sigf(gi.x + xi.x),     iB = sigf(gi.y + xi.y);
            float fA = sigf(gf.x + xf.x),     fB = sigf(gf.y + xf.y);
            float gA = tanhfast(gg.x + xg.x), gB = tanhfast(gg.y + xg.y);
            float oA = sigf(go.x + xo.x),     oB = sigf(go.y + xo.y);

            float cnA = fA * cst0 + iA * gA;
            float cnB = fB * cst1 + iB * gB;
            float hnA = oA * tanhfast(cnA);
            float hnB = oB * tanhfast(cnB);

            float2 ho; ho.x = hnA; ho.y = hnB;
            *reinterpret_cast<float2*>(&out[((size_t)t * B_ + b) * H_ + j]) = ho;

            float hwA, hwB, cwA, cwB;
            if (t + 1 < T_) {
                bool msk = (mskN != 0u);
                hwA = msk ? 0.f : hnA; cwA = msk ? 0.f : cnA;
                hwB = msk ? 0.f : hnB; cwB = msk ? 0.f : cnB;
                hwA += nzN.x * sN; cwA += nzN.x * sN;
                hwB += nzN.y * sN; cwB += nzN.y * sN;
            } else {
                hwA = hnA; cwA = cnA; hwB = hnB; cwB = cnB;
                float2 hv; hv.x = hnA; hv.y = hnB;
                float2 cv; cv.x = cnA; cv.y = cnB;
                *reinterpret_cast<float2*>(&out[(size_t)T_ * (B_ * H_) + b * H_ + j]) = hv;
                *reinterpret_cast<float2*>(&out[(size_t)T_ * (B_ * H_) + B_ * H_ + b * H_ + j]) = cv;
            }
            *reinterpret_cast<uint32_t*>(&g_h2[(t + 1) & 1][b * H_ + j]) = h2u(hwA, hwB);
            cst0 = cwA; cst1 = cwB;
        }

        __syncthreads();
        if (tid == 0)
            asm volatile("red.release.gpu.global.add.u32 [%0], %1;"
                         :: "l"(&bar[t + 1]), "r"(1u) : "memory");
    }

    // ---- cleanup: restore counters to zero for graph replays ----
    if (tid == 0 && cg == 0) {
        unsigned v;
        do {
            asm volatile("ld.acquire.gpu.global.u32 %0, [%1];"
                         : "=r"(v) : "l"(&bar[T_]) : "memory");
        } while (v < NG);
        bar[T_ - 1] = 0;
        bar[T_]     = 0;
    }
}

// ==========================================================================
extern "C" void kernel_launch(void* const* d_in, const int* in_sizes, int n_in,
                              void* d_out, int out_size) {
    (void)in_sizes; (void)n_in; (void)out_size;
    const float*    latent = (const float*)d_in[0];
    const float*    h0     = (const float*)d_in[1];
    const float*    c0     = (const float*)d_in[2];
    const uint32_t* reset  = (const uint32_t*)d_in[3];
    const uint32_t* clearm = (const uint32_t*)d_in[4];
    const float*    nstd   = (const float*)d_in[5];
    const float*    noise  = (const float*)d_in[6];
    const float*    w_ih   = (const float*)d_in[7];
    const float*    w_hh   = (const float*)d_in[8];
    const float*    b_ih   = (const float*)d_in[9];
    const float*    b_hh   = (const float*)d_in[10];
    float* out = (float*)d_out;

    const int smem1 = 512 + 20480 + 16384;             // 37376 B
    const int smem2 = 196608 + 16640 + 8448;           // 221696 B
    cudaFuncSetAttribute(xgemm_fp16, cudaFuncAttributeMaxDynamicSharedMemorySize, smem1);
    cudaFuncSetAttribute(lstm_rec16, cudaFuncAttributeMaxDynamicSharedMemorySize, smem2);

    xgemm_fp16<<<512 * 16, 256, smem1>>>(latent, w_ih, b_ih, b_hh);
    lstm_rec16<<<128, 256, smem2>>>(h0, c0, reset, clearm, nstd, noise, w_hh, out);
}

// round 5
// speedup vs baseline: 7.8661x; 1.1215x over previous
#include <cuda_runtime.h>
#include <cuda_fp16.h>
#include <cstdint>
#include <cstddef>

#define T_   512
#define B_   128
#define H_   512
#define G4   2048
#define NG   16      // CTAs per row-group (phase 2)

// ---------------- scratch (device globals; no allocation) ----------------
__device__ float    g_Xg[(size_t)T_ * B_ * G4];   // 512 MB: x@W_ih^T + b_ih + b_hh
__device__ __half   g_h2[2][B_ * H_];             // double-buffered fp16 h
__device__ unsigned g_bar[8 * 1024];              // per-group step counters (self-zeroing)

// ---------------- helpers ----------------
__device__ __forceinline__ void mma_f16(float c[4], const uint32_t a[4],
                                        uint32_t b0, uint32_t b1) {
    asm volatile(
        "mma.sync.aligned.m16n8k16.row.col.f32.f16.f16.f32 "
        "{%0,%1,%2,%3},{%4,%5,%6,%7},{%8,%9},{%0,%1,%2,%3};"
        : "+f"(c[0]), "+f"(c[1]), "+f"(c[2]), "+f"(c[3])
        : "r"(a[0]), "r"(a[1]), "r"(a[2]), "r"(a[3]), "r"(b0), "r"(b1));
}
__device__ __forceinline__ void ldsm4(uint32_t r[4], uint32_t saddr) {
    asm volatile("ldmatrix.sync.aligned.m8n8.x4.shared.b16 {%0,%1,%2,%3},[%4];"
        : "=r"(r[0]), "=r"(r[1]), "=r"(r[2]), "=r"(r[3]) : "r"(saddr));
}
__device__ __forceinline__ void cp16(uint32_t sdst, const void* gsrc) {
    asm volatile("cp.async.ca.shared.global [%0],[%1],16;" :: "r"(sdst), "l"(gsrc));
}
__device__ __forceinline__ uint32_t h2u(float x, float y) {
    __half2 h = __floats2half2_rn(x, y);
    return *reinterpret_cast<uint32_t*>(&h);
}
__device__ __forceinline__ int pidx(int p) { return (p & 3) * 2 + (p >> 2); }

__device__ __forceinline__ float sigf(float x) {
    return __fdividef(1.0f, 1.0f + __expf(-x));
}
__device__ __forceinline__ float tanhfast(float x) {
    return 1.0f - 2.0f * __fdividef(1.0f, __expf(2.0f * x) + 1.0f);
}

// ==========================================================================
// Phase 1: Xg[t,b,n] = latent[t,b,:] @ W_ih^T + (b_ih + b_hh)   (fp16 mma)
// ==========================================================================
__global__ void __launch_bounds__(256) xgemm_fp16(
    const float* __restrict__ latent,   // [T*B, 512]
    const float* __restrict__ w_ih,     // [2048, 512]
    const float* __restrict__ b_ih,
    const float* __restrict__ b_hh)
{
    extern __shared__ __align__(16) unsigned char sm[];
    float*    bias_s = (float*)sm;
    __half*   A0 = (__half*)(sm + 512);
    __half*   A1 = A0 + 5120;
    uint32_t* B0 = (uint32_t*)(sm + 512 + 20480);
    uint32_t* B1 = B0 + 2048;

    const int tid  = threadIdx.x;
    const int nt   = blockIdx.x & 15;
    const int tt   = blockIdx.x >> 4;
    const int n0   = nt * 128;
    const int lane = tid & 31, w = tid >> 5;
    const int mb   = (w & 3) * 32;
    const int nb2  = (w >> 2) * 64;

    if (tid < 128) bias_s[tid] = b_ih[n0 + tid] + b_hh[n0 + tid];

    const float* __restrict__ Xrow = latent + (size_t)tt * (128 * 512);

    float c[2][8][4];
    #pragma unroll
    for (int i = 0; i < 2; i++)
        #pragma unroll
        for (int j = 0; j < 8; j++)
            #pragma unroll
            for (int k = 0; k < 4; k++) c[i][j][k] = 0.f;

    float4 ra[4], rb[4];

    auto LD = [&](int kt) {
        int k0 = kt * 32;
        #pragma unroll
        for (int i = 0; i < 4; i++) {
            int idx = tid + i * 256;
            int r = idx >> 3, c4 = idx & 7;
            ra[i] = *reinterpret_cast<const float4*>(&Xrow[r * 512 + k0 + c4 * 4]);
            rb[i] = *reinterpret_cast<const float4*>(&w_ih[(size_t)(n0 + r) * 512 + k0 + c4 * 4]);
        }
    };
    auto ST = [&](__half* As, uint32_t* Bs) {
        #pragma unroll
        for (int i = 0; i < 4; i++) {
            int idx = tid + i * 256;
            int r = idx >> 3, c4 = idx & 7;
            uint2 av;
            av.x = h2u(ra[i].x, ra[i].y);
            av.y = h2u(ra[i].z, ra[i].w);
            *reinterpret_cast<uint2*>(&As[r * 40 + c4 * 4]) = av;
            int ks = c4 >> 2, pp = (c4 & 3) * 2;
            Bs[(ks * 128 + r) * 8 + pidx(pp)]     = h2u(rb[i].x, rb[i].y);
            Bs[(ks * 128 + r) * 8 + pidx(pp + 1)] = h2u(rb[i].z, rb[i].w);
        }
    };
    auto COMPUTE = [&](const __half* As, const uint32_t* Bs) {
        const uint32_t* Au = reinterpret_cast<const uint32_t*>(As);
        #pragma unroll
        for (int ks = 0; ks < 2; ++ks) {
            uint32_t a[2][4];
            #pragma unroll
            for (int mi = 0; mi < 2; mi++) {
                int base = (mb + mi * 16 + (lane >> 2)) * 20 + ks * 8 + (lane & 3);
                a[mi][0] = Au[base];       a[mi][1] = Au[base + 160];
                a[mi][2] = Au[base + 4];   a[mi][3] = Au[base + 164];
            }
            #pragma unroll
            for (int ni = 0; ni < 8; ++ni) {
                int n = nb2 + ni * 8 + (lane >> 2);
                uint2 bv = *reinterpret_cast<const uint2*>(&Bs[(ks * 128 + n) * 8 + (lane & 3) * 2]);
                mma_f16(c[0][ni], a[0], bv.x, bv.y);
                mma_f16(c[1][ni], a[1], bv.x, bv.y);
            }
        }
    };

    LD(0); ST(A0, B0); __syncthreads();
    int buf = 0;
    #pragma unroll 1
    for (int kt = 0; kt < 16; ++kt) {
        if (kt < 15) LD(kt + 1);
        COMPUTE(buf ? A1 : A0, buf ? B1 : B0);
        if (kt < 15) {
            ST(buf ? A0 : A1, buf ? B0 : B1);
            __syncthreads();
            buf ^= 1;
        }
    }

    #pragma unroll
    for (int mi = 0; mi < 2; mi++) {
        #pragma unroll
        for (int ni = 0; ni < 8; ni++) {
            int r    = mb + mi * 16 + (lane >> 2);
            int colL = nb2 + ni * 8 + (lane & 3) * 2;
            float bv0 = bias_s[colL], bv1 = bias_s[colL + 1];
            size_t base = ((size_t)(tt * 128 + r)) * G4 + n0 + colL;
            float2 v0; v0.x = c[mi][ni][0] + bv0; v0.y = c[mi][ni][1] + bv1;
            *reinterpret_cast<float2*>(&g_Xg[base]) = v0;
            float2 v1; v1.x = c[mi][ni][2] + bv0; v1.y = c[mi][ni][3] + bv1;
            *reinterpret_cast<float2*>(&g_Xg[base + (size_t)8 * G4]) = v1;
        }
    }
}

// ==========================================================================
// Phase 2: persistent recurrence, fp16 mma, W fragments resident in REGISTERS
// (zero per-step B smem traffic), in-warp shuffle epilogue (no gsm spill).
// 128 CTAs x 256 thr. CTA (mg,cg): rows [mg*16,+16), hidden cols [cg*32,+32).
// W column order per warp w (16 cols): tile0 = [i_j0..3 | f_j0..3],
// tile1 = [g_j0..3 | o_j0..3] where j = j0 + w*4 + joff. So after mma each
// warp holds all 4 gates for its own 4 h-columns -> shuffle exchange only.
// ==========================================================================
__global__ void __launch_bounds__(256, 1) lstm_rec16(
    const float*    __restrict__ h0,
    const float*    __restrict__ c0,
    const uint32_t* __restrict__ reset,    // [B,T]
    const uint32_t* __restrict__ clearm,   // [B,T]
    const float*    __restrict__ nstd,     // [B,T]
    const float*    __restrict__ noise,    // [T,B,H]
    const float*    __restrict__ w_hh,     // [2048,512]
    float*          __restrict__ out)
{
    extern __shared__ __align__(16) unsigned char sm[];
    __half* W_s = (__half*)sm;                       // 196608 B (init only)
    __half* A_s = (__half*)(sm + 196608);            // 16 x 520 halves

    const int tid  = threadIdx.x;
    const int cb   = blockIdx.x;
    const int mg   = cb >> 4, cg = cb & 15;
    const int b0   = mg * 16, j0 = cg * 32;
    const int lane = tid & 31, w = tid >> 5;

    unsigned* bar = &g_bar[mg * 1024];

    // ---- W_s fill (once), PERMUTED column order (see header comment)
    for (int e = tid; e < 4096; e += 256) {
        int ks = e >> 7, c = e & 127;
        int wp = c >> 4, idx = c & 15;
        int ti = idx >> 3, p = idx & 7;
        int n  = (ti * 2 + (p >> 2)) * 512 + j0 + wp * 4 + (p & 3);
        const float4* wpn = reinterpret_cast<const float4*>(&w_hh[(size_t)n * 512 + ks * 16]);
        float4 w0 = wpn[0], w1 = wpn[1], w2 = wpn[2], w3 = wpn[3];
        uint4 lo, hi;
        lo.x = h2u(w0.x, w0.y); lo.y = h2u(w0.z, w0.w);
        lo.z = h2u(w1.x, w1.y); lo.w = h2u(w1.z, w1.w);
        hi.x = h2u(w2.x, w2.y); hi.y = h2u(w2.z, w2.w);
        hi.z = h2u(w3.x, w3.y); hi.w = h2u(w3.z, w3.w);
        char* base = (char*)W_s + (size_t)(ks * 128 + c) * 48;
        *reinterpret_cast<uint4*>(base)      = lo;
        *reinterpret_cast<uint4*>(base + 16) = hi;
    }
    __syncthreads();

    // ---- LDSM fragment addressing
    const uint32_t Ws_sa = (uint32_t)__cvta_generic_to_shared(W_s);
    const uint32_t As_sa = (uint32_t)__cvta_generic_to_shared(A_s);
    const int mq   = lane >> 3, rl = lane & 7;
    const int rowL = (mq & 1) * 8 + rl;
    const int koff = (mq >> 1) * 8;
    const uint32_t aAddr0 = As_sa + rowL * 1040 + koff * 2;
    const uint32_t bAddr0 = Ws_sa + (w * 16 + rowL) * 48 + koff * 2;

    // ---- load ALL W fragments into registers (persist across all steps)
    uint32_t bb[32][4];
    #pragma unroll
    for (int ks = 0; ks < 32; ++ks)
        ldsm4(bb[ks], bAddr0 + ks * 6144);

    // ---- epilogue lane mapping: lane handles rows rE, rE+8; col j
    const int rE = lane >> 2, jE = lane & 3;
    const int bA = b0 + rE, bB = bA + 8;
    const int j  = j0 + w * 4 + jE;
    const int sA = (lane & 28) | (jE >> 1);
    const int sB = sA | 2;
    const unsigned FM = 0xFFFFFFFFu;

    // ---- init h/c with step-0 preprocessing; c stays in regs
    float cst0, cst1;
    {
        float hA = h0[bA * H_ + j], cA = c0[bA * H_ + j];
        float hB = h0[bB * H_ + j], cB = c0[bB * H_ + j];
        bool mA = ((reset[bA * T_] | clearm[bA * T_]) != 0u);
        bool mB = ((reset[bB * T_] | clearm[bB * T_]) != 0u);
        if (mA) { hA = cA = 0.f; }
        if (mB) { hB = cB = 0.f; }
        float nzA = noise[(size_t)bA * H_ + j] * nstd[bA * T_];
        float nzB = noise[(size_t)bB * H_ + j] * nstd[bB * T_];
        hA += nzA; cA += nzA;
        hB += nzB; cB += nzB;
        g_h2[0][bA * H_ + j] = __float2half_rn(hA);
        g_h2[0][bB * H_ + j] = __float2half_rn(hB);
        cst0 = cA; cst1 = cB;
    }
    __syncthreads();
    if (tid == 0)
        asm volatile("red.release.gpu.global.add.u32 [%0], %1;" :: "l"(&bar[0]), "r"(1u) : "memory");

    // staging map: 4 x 16B per thread
    const int stR = tid >> 6;
    const int stC = tid & 63;

    for (int t = 0; t < T_; ++t) {
        // ---- prefetch (independent of h[t]) ----
        size_t xbA = ((size_t)t * B_ + bA) * G4 + j;
        size_t xbB = ((size_t)t * B_ + bB) * G4 + j;
        float xI0 = g_Xg[xbA],        xI1 = g_Xg[xbB];
        float xF0 = g_Xg[xbA + 512],  xF1 = g_Xg[xbB + 512];
        float xG0 = g_Xg[xbA + 1024], xG1 = g_Xg[xbB + 1024];
        float xO0 = g_Xg[xbA + 1536], xO1 = g_Xg[xbB + 1536];
        unsigned mN0 = 0, mN1 = 0;
        float sN0 = 0.f, sN1 = 0.f, nz0 = 0.f, nz1 = 0.f;
        if (t + 1 < T_) {
            mN0 = reset[bA * T_ + t + 1] | clearm[bA * T_ + t + 1];
            mN1 = reset[bB * T_ + t + 1] | clearm[bB * T_ + t + 1];
            sN0 = nstd[bA * T_ + t + 1];
            sN1 = nstd[bB * T_ + t + 1];
            nz0 = noise[((size_t)(t + 1) * B_ + bA) * H_ + j];
            nz1 = noise[((size_t)(t + 1) * B_ + bB) * H_ + j];
        }

        // ---- wait for h[t] ----
        if (tid == 0) {
            unsigned v;
            do {
                asm volatile("ld.acquire.gpu.global.u32 %0, [%1];"
                             : "=r"(v) : "l"(&bar[t]) : "memory");
            } while (v < NG);
            if (cg == 0 && t >= 1) bar[t - 1] = 0;
        }
        __syncthreads();

        // ---- stage h tile [16][512] fp16 via cp.async ----
        const __half* __restrict__ hsrc = g_h2[t & 1];
        #pragma unroll
        for (int i = 0; i < 4; i++) {
            int r = stR + i * 4;
            cp16(As_sa + r * 1040 + stC * 16, &hsrc[(b0 + r) * H_ + stC * 8]);
        }
        asm volatile("cp.async.commit_group;");
        asm volatile("cp.async.wait_group 0;");
        __syncthreads();

        // ---- GEMM: 32 ksteps, per warp: LDSM.x4 A + 2 mma (B from regs) ----
        float acc0[4] = {0.f, 0.f, 0.f, 0.f};
        float acc1[4] = {0.f, 0.f, 0.f, 0.f};
        #pragma unroll
        for (int ks = 0; ks < 32; ++ks) {
            uint32_t a[4];
            ldsm4(a, aAddr0 + ks * 32);
            mma_f16(acc0, a, bb[ks][0], bb[ks][2]);
            mma_f16(acc1, a, bb[ks][1], bb[ks][3]);
        }

        // ---- in-warp gate exchange (16 shfl; no smem, no sync) ----
        float u0, u1;
        u0 = __shfl_sync(FM, acc0[0], sA); u1 = __shfl_sync(FM, acc0[1], sA);
        float gi0 = (jE & 1) ? u1 : u0;
        u0 = __shfl_sync(FM, acc0[2], sA); u1 = __shfl_sync(FM, acc0[3], sA);
        float gi1 = (jE & 1) ? u1 : u0;
        u0 = __shfl_sync(FM, acc0[0], sB); u1 = __shfl_sync(FM, acc0[1], sB);
        float gf0 = (jE & 1) ? u1 : u0;
        u0 = __shfl_sync(FM, acc0[2], sB); u1 = __shfl_sync(FM, acc0[3], sB);
        float gf1 = (jE & 1) ? u1 : u0;
        u0 = __shfl_sync(FM, acc1[0], sA); u1 = __shfl_sync(FM, acc1[1], sA);
        float gg0 = (jE & 1) ? u1 : u0;
        u0 = __shfl_sync(FM, acc1[2], sA); u1 = __shfl_sync(FM, acc1[3], sA);
        float gg1 = (jE & 1) ? u1 : u0;
        u0 = __shfl_sync(FM, acc1[0], sB); u1 = __shfl_sync(FM, acc1[1], sB);
        float go0 = (jE & 1) ? u1 : u0;
        u0 = __shfl_sync(FM, acc1[2], sB); u1 = __shfl_sync(FM, acc1[3], sB);
        float go1 = (jE & 1) ? u1 : u0;

        // ---- gates + state update + next-step preprocessing ----
        float iA = sigf(gi0 + xI0),     iB = sigf(gi1 + xI1);
        float fA = sigf(gf0 + xF0),     fB = sigf(gf1 + xF1);
        float gA = tanhfast(gg0 + xG0), gB = tanhfast(gg1 + xG1);
        float oA = sigf(go0 + xO0),     oB = sigf(go1 + xO1);

        float cnA = fA * cst0 + iA * gA;
        float cnB = fB * cst1 + iB * gB;
        float hnA = oA * tanhfast(cnA);
        float hnB = oB * tanhfast(cnB);

        float hwA, hwB, cwA, cwB;
        if (t + 1 < T_) {
            hwA = mN0 ? 0.f : hnA; cwA = mN0 ? 0.f : cnA;
            hwB = mN1 ? 0.f : hnB; cwB = mN1 ? 0.f : cnB;
            hwA += nz0 * sN0; cwA += nz0 * sN0;
            hwB += nz1 * sN1; cwB += nz1 * sN1;
        } else {
            hwA = hnA; cwA = cnA; hwB = hnB; cwB = cnB;
        }
        g_h2[(t + 1) & 1][bA * H_ + j] = __float2half_rn(hwA);
        g_h2[(t + 1) & 1][bB * H_ + j] = __float2half_rn(hwB);
        cst0 = cwA; cst1 = cwB;

        __syncthreads();
        if (tid == 0)
            asm volatile("red.release.gpu.global.add.u32 [%0], %1;"
                         :: "l"(&bar[t + 1]), "r"(1u) : "memory");

        // ---- off-critical-path stores ----
        out[((size_t)t * B_ + bA) * H_ + j] = hnA;
        out[((size_t)t * B_ + bB) * H_ + j] = hnB;
        if (t == T_ - 1) {
            out[(size_t)T_ * (B_ * H_)           + bA * H_ + j] = hnA;
            out[(size_t)T_ * (B_ * H_)           + bB * H_ + j] = hnB;
            out[(size_t)T_ * (B_ * H_) + B_ * H_ + bA * H_ + j] = cnA;
            out[(size_t)T_ * (B_ * H_) + B_ * H_ + bB * H_ + j] = cnB;
        }
    }

    // ---- cleanup: restore counters to zero for graph replays ----
    if (tid == 0 && cg == 0) {
        unsigned v;
        do {
            asm volatile("ld.acquire.gpu.global.u32 %0, [%1];"
                         : "=r"(v) : "l"(&bar[T_]) : "memory");
        } while (v < NG);
        bar[T_ - 1] = 0;
        bar[T_]     = 0;
    }
}

// ==========================================================================
extern "C" void kernel_launch(void* const* d_in, const int* in_sizes, int n_in,
                              void* d_out, int out_size) {
    (void)in_sizes; (void)n_in; (void)out_size;
    const float*    latent = (const float*)d_in[0];
    const float*    h0     = (const float*)d_in[1];
    const float*    c0     = (const float*)d_in[2];
    const uint32_t* reset  = (const uint32_t*)d_in[3];
    const uint32_t* clearm = (const uint32_t*)d_in[4];
    const float*    nstd   = (const float*)d_in[5];
    const float*    noise  = (const float*)d_in[6];
    const float*    w_ih   = (const float*)d_in[7];
    const float*    w_hh   = (const float*)d_in[8];
    const float*    b_ih   = (const float*)d_in[9];
    const float*    b_hh   = (const float*)d_in[10];
    float* out = (float*)d_out;

    const int smem1 = 512 + 20480 + 16384;             // 37376 B
    const int smem2 = 196608 + 16640;                  // 213248 B
    cudaFuncSetAttribute(xgemm_fp16, cudaFuncAttributeMaxDynamicSharedMemorySize, smem1);
    cudaFuncSetAttribute(lstm_rec16, cudaFuncAttributeMaxDynamicSharedMemorySize, smem2);

    xgemm_fp16<<<512 * 16, 256, smem1>>>(latent, w_ih, b_ih, b_hh);
    lstm_rec16<<<128, 256, smem2>>>(h0, c0, reset, clearm, nstd, noise, w_hh, out);
}